// round 8
// baseline (speedup 1.0000x reference)
#include <cuda_runtime.h>

// ContrastivePredictionLoss — two-kernel + PDL overlap, R8 (retry of R7 after
// broker/container failure; added a fallback plain launch if cudaLaunchKernelEx
// errors at capture time).
//
// Stage A: proven streaming reduce (~6.2 TB/s), triggers programmatic launch
//          completion right after its loads so stage B's launch ramp overlaps
//          the reduce tail.
// Stage B: finalize waits on cudaGridDependencySynchronize() (full primary-grid
//          completion — correctness identical), then reads interleaved float2
//          partials with 4 independent LDG.128 per thread.

#define NB 64
#define ELEMS_PER_BATCH (4 * 256 * 256)      // 262144
#define BLOCKS_PER_BATCH 32
#define NBLOCKS (NB * BLOCKS_PER_BATCH)      // 2048
#define THREADS_A 256
#define ELEMS_PER_BLOCK (ELEMS_PER_BATCH / BLOCKS_PER_BATCH)   // 8192
#define VECS_PER_BLOCK (ELEMS_PER_BLOCK / 4)                   // 2048 float4
#define VECS_PER_THREAD (VECS_PER_BLOCK / THREADS_A)           // 8

// Scratch (allocation-free __device__ global). x = err partial, y = unc partial.
__device__ float2 g_part[NBLOCKS];

__global__ __launch_bounds__(THREADS_A)
void cpl_reduce_kernel(const float4* __restrict__ pm,
                       const float4* __restrict__ ps,
                       const float4* __restrict__ tg) {
    const int blk = blockIdx.x;                      // b * 32 + chunk
    const int tid = threadIdx.x;
    const long base = (long)blk * VECS_PER_BLOCK;

    float se = 0.0f;   // sum |pm - tg|
    float su = 0.0f;   // sum ps

    #pragma unroll
    for (int i = 0; i < VECS_PER_THREAD; i++) {
        const long idx = base + (long)i * THREADS_A + tid;
        float4 m = pm[idx];
        float4 t = tg[idx];
        float4 s = ps[idx];
        se += fabsf(m.x - t.x) + fabsf(m.y - t.y)
            + fabsf(m.z - t.z) + fabsf(m.w - t.w);
        su += s.x + s.y + s.z + s.w;
    }

    // Loads done — let the dependent finalize kernel begin its launch ramp.
    cudaTriggerProgrammaticLaunchCompletion();

    // Warp reduce (deterministic shuffle tree)
    #pragma unroll
    for (int off = 16; off > 0; off >>= 1) {
        se += __shfl_down_sync(0xFFFFFFFFu, se, off);
        su += __shfl_down_sync(0xFFFFFFFFu, su, off);
    }

    __shared__ float s_se[THREADS_A / 32];
    __shared__ float s_su[THREADS_A / 32];
    const int wid = tid >> 5;
    const int lid = tid & 31;
    if (lid == 0) { s_se[wid] = se; s_su[wid] = su; }
    __syncthreads();

    if (wid == 0) {
        se = (lid < THREADS_A / 32) ? s_se[lid] : 0.0f;
        su = (lid < THREADS_A / 32) ? s_su[lid] : 0.0f;
        #pragma unroll
        for (int off = 4; off > 0; off >>= 1) {
            se += __shfl_down_sync(0xFFFFFFFFu, se, off);
            su += __shfl_down_sync(0xFFFFFFFFu, su, off);
        }
        if (lid == 0) {
            g_part[blk] = make_float2(se, su);
        }
    }
}

#define THREADS_B 256

__global__ __launch_bounds__(THREADS_B)
void cpl_finalize_kernel(float* __restrict__ out) {
    // Block until the ENTIRE reduce grid has completed (PDL semantics).
    // Under a conventional (fallback) launch this returns immediately and
    // stream ordering provides the dependency instead.
    cudaGridDependencySynchronize();

    const int tid = threadIdx.x;
    const int wid = tid >> 5;
    const int lid = tid & 31;

    // 2048 float2 partials = 1024 float4. Thread -> batch b = tid>>2,
    // quarter q = tid&3: 4 independent float4 = 8 partials
    // (batch b occupies float4 indices [b*16, b*16+16)).
    const int b = tid >> 2;
    const int q = tid & 3;
    const float4* p4 = (const float4*)g_part;

    float pe = 0.0f, pu = 0.0f;
    #pragma unroll
    for (int k = 0; k < 4; k++) {
        float4 v = p4[b * 16 + q * 4 + k];   // {err,unc,err,unc}
        pe += v.x + v.z;
        pu += v.y + v.w;
    }

    __shared__ float s_pe[4][NB];
    __shared__ float s_pu[4][NB];
    s_pe[q][b] = pe;
    s_pu[q][b] = pu;
    __syncthreads();

    __shared__ float errs[NB];
    __shared__ float uncs[NB];
    if (tid < NB) {
        const float inv = 1.0f / (float)ELEMS_PER_BATCH;
        errs[tid] = ((s_pe[0][tid] + s_pe[1][tid]) + (s_pe[2][tid] + s_pe[3][tid])) * inv;
        uncs[tid] = ((s_pu[0][tid] + s_pu[1][tid]) + (s_pu[2][tid] + s_pu[3][tid])) * inv;
    }
    __syncthreads();

    // Pairwise hinge over upper triangle (i < j), fixed iteration order.
    float acc = 0.0f;
    #pragma unroll
    for (int p = tid; p < NB * NB; p += THREADS_B) {
        const int i = p >> 6;
        const int j = p & 63;
        if (i < j) {
            const float d = ((errs[i] > errs[j]) ? (uncs[j] - uncs[i])
                                                 : (uncs[i] - uncs[j])) + 1.0f;
            acc += fmaxf(d, 0.0f);
        }
    }

    #pragma unroll
    for (int off = 16; off > 0; off >>= 1)
        acc += __shfl_down_sync(0xFFFFFFFFu, acc, off);

    __shared__ float s_acc[THREADS_B / 32];
    if (lid == 0) s_acc[wid] = acc;
    __syncthreads();

    if (tid == 0) {
        float total = 0.0f;
        #pragma unroll
        for (int w = 0; w < THREADS_B / 32; w++) total += s_acc[w];
        const int num_pairs = NB * (NB - 1) / 2;   // 2016
        out[0] = total / (float)num_pairs;
    }
}

extern "C" void kernel_launch(void* const* d_in, const int* in_sizes, int n_in,
                              void* d_out, int out_size) {
    const float4* pm = (const float4*)d_in[0];   // pred_mean
    const float4* ps = (const float4*)d_in[1];   // pred_std
    const float4* tg = (const float4*)d_in[2];   // targets
    float* out = (float*)d_out;

    cpl_reduce_kernel<<<NBLOCKS, THREADS_A>>>(pm, ps, tg);

    // Finalize with programmatic dependent launch: overlap its launch ramp
    // with the reduce grid's tail; gridsync inside preserves ordering.
    cudaLaunchConfig_t cfg = {};
    cfg.gridDim = dim3(1, 1, 1);
    cfg.blockDim = dim3(THREADS_B, 1, 1);
    cfg.dynamicSmemBytes = 0;
    cfg.stream = 0;
    cudaLaunchAttribute attrs[1];
    attrs[0].id = cudaLaunchAttributeProgrammaticStreamSerialization;
    attrs[0].val.programmaticStreamSerializationAllowed = 1;
    cfg.attrs = attrs;
    cfg.numAttrs = 1;
    cudaError_t err = cudaLaunchKernelEx(&cfg, cpl_finalize_kernel, out);
    if (err != cudaSuccess) {
        // Fallback: conventional launch (no overlap, stream-ordered, correct).
        cpl_finalize_kernel<<<1, THREADS_B>>>(out);
    }
}